// round 5
// baseline (speedup 1.0000x reference)
#include <cuda_runtime.h>
#include <cuda_bf16.h>
#include <cstdint>

// HONU order-2: out[i] = sum_{j<=k} W[p(j,k)] * x[i,j] * x[i,k] + b
// p(j,k) = j*64 - j*(j-1)/2 + (k-j)
//
// Round 5: Round-4 design with the h-offset bug fixed (x base now also
// carries the parity offset). Pre-kernel expands W into padded A_g[64x72];
// main kernel: 8 lanes/row (t = j mod 4, h = q-parity), stride-72 smem,
// all LDS conflict-free, zero-padded tails (no predication), packed f32x2
// math. 1024 blocks x 128 threads -> 4096 warps (~43% occ).

#define AST   72                 // padded row stride in floats (18 float4s)
#define RPB   16                 // rows per block
#define THREADS 128

__device__ __align__(16) float A_g[64 * AST];

__global__ void expand_kernel(const float* __restrict__ W) {
    int i = blockIdx.x * THREADS + threadIdx.x;     // 4608 slots
    if (i < 64 * AST) {
        int j = i / AST, k = i - j * AST;
        float v = 0.0f;
        if (k >= j && k < 64)
            v = W[j * 64 - ((j * (j - 1)) >> 1) + (k - j)];
        A_g[i] = v;
    }
}

__device__ __forceinline__ void lds_v2u64(uint64_t& a, uint64_t& b, unsigned addr) {
    asm volatile("ld.shared.v2.b64 {%0,%1}, [%2];" : "=l"(a), "=l"(b) : "r"(addr));
}
__device__ __forceinline__ void fma2(uint64_t& d, uint64_t a, uint64_t b) {
    asm volatile("fma.rn.f32x2 %0, %1, %2, %0;" : "+l"(d) : "l"(a), "l"(b));
}
__device__ __forceinline__ uint64_t add2(uint64_t a, uint64_t b) {
    uint64_t d;
    asm volatile("add.rn.f32x2 %0, %1, %2;" : "=l"(d) : "l"(a), "l"(b));
    return d;
}

__global__ void __launch_bounds__(THREADS, 7) honu_kernel(
    const float* __restrict__ x, const float* __restrict__ b,
    float* __restrict__ out)
{
    __shared__ __align__(16) float A[64 * AST];    // 18.0 KB
    __shared__ __align__(16) float xs[RPB * AST];  //  4.5 KB

    const int tid  = threadIdx.x;
    const int row0 = blockIdx.x * RPB;

    // --- Copy pre-expanded A (1152 float4s, 9 per thread, coalesced)
    {
        const float4* Ag4 = reinterpret_cast<const float4*>(A_g);
        float4*       As4 = reinterpret_cast<float4*>(A);
        #pragma unroll
        for (int it = 0; it < 9; ++it)
            As4[it * THREADS + tid] = Ag4[it * THREADS + tid];
    }
    // --- Stage x tile with zero pad: 16 rows x 18 float4 (cols 64..71 = 0)
    {
        const float4* xg4 = reinterpret_cast<const float4*>(x + (size_t)row0 * 64);
        float4*       xs4 = reinterpret_cast<float4*>(xs);
        const float4  z4  = make_float4(0.f, 0.f, 0.f, 0.f);
        #pragma unroll
        for (int it = 0; it < 3; ++it) {
            int i = it * THREADS + tid;            // 0..383, guard at 288
            if (i < RPB * (AST / 4)) {
                int rr = i / 18, c = i - rr * 18;
                xs4[i] = (c < 16) ? xg4[rr * 16 + c] : z4;
            }
        }
    }
    __syncthreads();

    const int lane = tid & 31;
    const int t    = lane & 3;              // j = 4*jj + t
    const int h    = (lane >> 2) & 1;       // q-parity slot
    const int r    = ((tid >> 5) << 2) + (lane >> 3);   // local row 0..15

    // BOTH bases carry the h parity offset (this was the R4 bug).
    const unsigned xa = (unsigned)__cvta_generic_to_shared(xs)
                        + r * (AST * 4) + h * 16;
    const unsigned Aa = (unsigned)__cvta_generic_to_shared(A)
                        + t * (AST * 4) + h * 16;

    // --- Quadratic form: j = 4jj+t; q = jj + h + 2k, k < (17-jj)>>1.
    //     Ragged tail q=16 reads the zero pad (contributes 0).
    uint64_t acc = 0;
    #pragma unroll
    for (int jj = 0; jj < 16; ++jj) {
        const unsigned wq = Aa + jj * (4 * AST * 4) + jj * 16;  // A[4jj+t][jj+h]
        const unsigned xq = xa + jj * 16;                       // xs[r][jj+h]
        uint64_t i01 = 0, i23 = 0;
        const int kmax = (17 - jj) >> 1;
        #pragma unroll
        for (int k = 0; k < kmax; ++k) {
            uint64_t w01, w23, x01, x23;
            lds_v2u64(w01, w23, wq + k * 32);
            lds_v2u64(x01, x23, xq + k * 32);
            fma2(i01, w01, x01);
            fma2(i23, w23, x23);
        }
        float xj = xs[r * AST + 4 * jj + t];   // bank 8r+t mod 32: conflict-free
        uint64_t xj2;
        asm volatile("mov.b64 %0, {%1,%1};" : "=l"(xj2) : "r"(__float_as_uint(xj)));
        fma2(acc, xj2, add2(i01, i23));
    }

    // --- Reduce: pack halves, then h (xor 4) and t (xor 1,2)
    uint32_t lo, hi;
    asm volatile("mov.b64 {%0,%1}, %2;" : "=r"(lo), "=r"(hi) : "l"(acc));
    float a = __uint_as_float(lo) + __uint_as_float(hi);
    a += __shfl_xor_sync(0xffffffffu, a, 4);
    a += __shfl_xor_sync(0xffffffffu, a, 1);
    a += __shfl_xor_sync(0xffffffffu, a, 2);

    if ((lane & 7) == 0) out[row0 + r] = a + b[0];
}

extern "C" void kernel_launch(void* const* d_in, const int* in_sizes, int n_in,
                              void* d_out, int out_size) {
    const float* x = (const float*)d_in[0];   // (16384, 64) f32
    const float* W = (const float*)d_in[1];   // (2145,)  f32 (first 2080 used)
    const float* b = (const float*)d_in[2];   // (1,)     f32
    float*     out = (float*)d_out;           // (16384,) f32

    expand_kernel<<<(64 * AST + THREADS - 1) / THREADS, THREADS>>>(W);

    const int nrows  = out_size;                     // 16384
    const int blocks = (nrows + RPB - 1) / RPB;      // 1024
    honu_kernel<<<blocks, THREADS>>>(x, b, out);
}